// round 1
// baseline (speedup 1.0000x reference)
#include <cuda_runtime.h>
#include <math.h>

#define NB   16
#define LL   512
#define DM   512
#define DI   1024
#define DS   16
#define DTR  32
#define ROWS (NB*LL)   // 8192

// ---------------- scratch (static device globals; no allocation) ----------------
__device__ float g_xmean[NB*DM];
__device__ float g_gf[NB*128];
__device__ float g_h1[NB*DM];
__device__ float g_h2[NB*DM];
__device__ float g_dA[NB*DM];
__device__ float g_dB[NB*DM];
__device__ float g_dC[NB*DM];
__device__ float g_hn[ROWS*DM];        // rmsnorm output; later reused for out_mm
__device__ float g_xz[ROWS*2*DI];      // W_in output: cols [0,1024)=xs_, [1024,2048)=z
__device__ float g_xc[ROWS*DI];        // conv+silu output; later reused for ys
__device__ float g_dbl[ROWS*64];       // xproj output: [0,32)=dtraw, [32,48)=B, [48,64)=C
__device__ float g_dt[ROWS*DI];        // softplus(dt)
__device__ float g_y[ROWS*DI];         // scan output accumulator

// ---------------- helpers ----------------
__device__ __forceinline__ float geluf(float x){
    return 0.5f*x*(1.0f + erff(x*0.70710678118654752f));
}
__device__ __forceinline__ float siluf(float x){
    return x / (1.0f + __expf(-x));
}
__device__ __forceinline__ float softplusf(float x){
    return (x > 20.0f) ? x : log1pf(__expf(x));
}

// ---------------- K1: mean over L ----------------
__global__ void k_mean(const float* __restrict__ x){
    int n = blockIdx.x, j = threadIdx.x;           // 16 blocks x 512 threads
    const float* p = x + (size_t)n*LL*DM + j;
    float s = 0.f;
    #pragma unroll 8
    for (int t = 0; t < LL; t++) s += p[(size_t)t*DM];
    g_xmean[n*DM + j] = s * (1.0f/LL);
}

// ---------------- K2a: gf = gelu(xmean @ W_gf.T + b_gf) ----------------
__global__ void k_gf(const float* __restrict__ Wgf, const float* __restrict__ bgf){
    __shared__ float sx[DM];
    int n = blockIdx.x, j = threadIdx.x;           // 16 blocks x 128 threads
    for (int k = j; k < DM; k += 128) sx[k] = g_xmean[n*DM + k];
    __syncthreads();
    const float* w = Wgf + (size_t)j*DM;
    float s = bgf[j];
    #pragma unroll 4
    for (int k = 0; k < DM; k++) s += sx[k]*w[k];
    g_gf[n*128 + j] = geluf(s);
}

// ---------------- K2b: h1 = gelu([gf, emb[sid]] @ W1.T + b1) ----------------
__global__ void k_h1(const float* __restrict__ W1, const float* __restrict__ b1,
                     const float* __restrict__ emb, const int* __restrict__ sid){
    __shared__ float sc[256];
    int n = blockIdx.x, j = threadIdx.x;           // 16 x 512
    if (j < 128) sc[j] = g_gf[n*128 + j];
    else if (j < 256) sc[j] = emb[sid[0]*128 + (j-128)];
    __syncthreads();
    const float* w = W1 + (size_t)j*256;
    float s = b1[j];
    #pragma unroll 4
    for (int k = 0; k < 256; k++) s += sc[k]*w[k];
    g_h1[n*DM + j] = geluf(s);
}

// ---------------- K2c: h2 = gelu(h1 @ W2.T + b2) ----------------
__global__ void k_h2(const float* __restrict__ W2, const float* __restrict__ b2){
    __shared__ float sh[DM];
    int n = blockIdx.x, j = threadIdx.x;           // 16 x 512
    sh[j] = g_h1[n*DM + j];
    __syncthreads();
    const float* w = W2 + (size_t)j*DM;
    float s = b2[j];
    #pragma unroll 4
    for (int k = 0; k < DM; k++) s += sh[k]*w[k];
    g_h2[n*DM + j] = geluf(s);
}

// ---------------- K2d: off = h2 @ W3.T + b3; per-chunk LayerNorm -> dA*sc, dB, dC ----
__global__ void k_off(const float* __restrict__ W3, const float* __restrict__ b3,
                      const float* __restrict__ lng, const float* __restrict__ lnb,
                      const int* __restrict__ sid){
    __shared__ float sh[DM];
    __shared__ float r1[16], r2[16];
    int n = blockIdx.x, c = blockIdx.y, j = threadIdx.x;   // (16,3) x 512
    sh[j] = g_h2[n*DM + j];
    __syncthreads();
    int row = c*DM + j;
    const float* w = W3 + (size_t)row*DM;
    float s = b3[row];
    #pragma unroll 4
    for (int k = 0; k < DM; k++) s += sh[k]*w[k];
    // block reduce sum / sumsq
    float s1 = s, s2 = s*s;
    #pragma unroll
    for (int o = 16; o > 0; o >>= 1){
        s1 += __shfl_xor_sync(0xffffffffu, s1, o);
        s2 += __shfl_xor_sync(0xffffffffu, s2, o);
    }
    int wid = j >> 5, ln = j & 31;
    if (ln == 0){ r1[wid] = s1; r2[wid] = s2; }
    __syncthreads();
    if (j < 16){
        float a = r1[j], b = r2[j];
        #pragma unroll
        for (int o = 8; o > 0; o >>= 1){
            a += __shfl_xor_sync(0x0000ffffu, a, o);
            b += __shfl_xor_sync(0x0000ffffu, b, o);
        }
        if (j == 0){ r1[0] = a; r2[0] = b; }
    }
    __syncthreads();
    float mu  = r1[0] * (1.0f/DM);
    float var = r2[0] * (1.0f/DM) - mu*mu;
    float v = (s - mu) * rsqrtf(var + 1e-5f) * lng[j] + lnb[j];
    if (c == 0){
        float scv = 0.9f - 0.3f*(float)sid[0];   // linspace(0.9,0.3,3)[sid]
        g_dA[n*DM + j] = v * scv;
    } else if (c == 1) g_dB[n*DM + j] = v;
    else               g_dC[n*DM + j] = v;
}

// ---------------- K3: residual = x + dB (+h_init at t=0); hn = rmsnorm(residual) ----
__global__ void k_res(const float* __restrict__ x, const float* __restrict__ hinit,
                      const float* __restrict__ rmsw, float* __restrict__ resid){
    __shared__ float red[16];
    int m = blockIdx.x, j = threadIdx.x;     // 8192 x 512
    int n = m >> 9, t = m & 511;
    float v = x[(size_t)m*DM + j] + g_dB[n*DM + j];
    if (t == 0) v += hinit[n*DM + j];
    resid[(size_t)m*DM + j] = v;
    float s2 = v*v;
    #pragma unroll
    for (int o = 16; o > 0; o >>= 1) s2 += __shfl_xor_sync(0xffffffffu, s2, o);
    int wid = j >> 5, ln = j & 31;
    if (ln == 0) red[wid] = s2;
    __syncthreads();
    if (j < 16){
        float a = red[j];
        #pragma unroll
        for (int o = 8; o > 0; o >>= 1) a += __shfl_xor_sync(0x0000ffffu, a, o);
        if (j == 0) red[0] = a;
    }
    __syncthreads();
    float rs = rsqrtf(red[0]*(1.0f/DM) + 1e-5f);
    g_hn[(size_t)m*DM + j] = v * rs * rmsw[j];
}

// ---------------- tiled fp32 GEMM: C[M,N] = A[M,K(lda)] * B[N,K(ldb)]^T ----------------
// EPI==1: C = softplus(C + bias[col])
template<int BM,int BN,int BK,int TM,int TN,int EPI>
__global__ void __launch_bounds__(256) gemm_nt(
    const float* __restrict__ A, int lda,
    const float* __restrict__ B, int ldb,
    float* __restrict__ C, int ldc,
    int K, const float* __restrict__ bias)
{
    __shared__ float As[BK][BM];
    __shared__ float Bs[BK][BN];
    int tid = threadIdx.x;
    int bm0 = blockIdx.y*BM, bn0 = blockIdx.x*BN;
    constexpr int TX = BN/TN;
    int tx = tid % TX, ty = tid / TX;
    float acc[TM][TN];
    #pragma unroll
    for (int i = 0; i < TM; i++)
        #pragma unroll
        for (int j = 0; j < TN; j++) acc[i][j] = 0.f;

    for (int k0 = 0; k0 < K; k0 += BK){
        #pragma unroll
        for (int i = tid*4; i < BM*BK; i += 256*4){
            int r = i / BK, c = i % BK;
            float4 v = *(const float4*)&A[(size_t)(bm0+r)*lda + k0 + c];
            As[c][r]=v.x; As[c+1][r]=v.y; As[c+2][r]=v.z; As[c+3][r]=v.w;
        }
        #pragma unroll
        for (int i = tid*4; i < BN*BK; i += 256*4){
            int r = i / BK, c = i % BK;
            float4 v = *(const float4*)&B[(size_t)(bn0+r)*ldb + k0 + c];
            Bs[c][r]=v.x; Bs[c+1][r]=v.y; Bs[c+2][r]=v.z; Bs[c+3][r]=v.w;
        }
        __syncthreads();
        #pragma unroll
        for (int kk = 0; kk < BK; kk++){
            float ra[TM], rb[TN];
            #pragma unroll
            for (int i = 0; i < TM; i++) ra[i] = As[kk][ty*TM + i];
            #pragma unroll
            for (int j = 0; j < TN; j++) rb[j] = Bs[kk][tx*TN + j];
            #pragma unroll
            for (int i = 0; i < TM; i++)
                #pragma unroll
                for (int j = 0; j < TN; j++) acc[i][j] += ra[i]*rb[j];
        }
        __syncthreads();
    }
    #pragma unroll
    for (int i = 0; i < TM; i++){
        int row = bm0 + ty*TM + i;
        #pragma unroll
        for (int j = 0; j < TN; j++){
            int col = bn0 + tx*TN + j;
            float v = acc[i][j];
            if (EPI == 1){ v += bias[col]; v = softplusf(v); }
            C[(size_t)row*ldc + col] = v;
        }
    }
}

// ---------------- depthwise causal conv + silu (REV handles sequence flip) ----------
template<int REV>
__global__ void k_conv(const float* __restrict__ cw, const float* __restrict__ cb){
    int m = blockIdx.x;                     // scan-time position n*512+t
    int n = m >> 9, t = m & 511;
    int d = blockIdx.y*256 + threadIdx.x;   // (8192,4) x 256
    const float* w = cw + d*4;
    float s = cb[d];
    #pragma unroll
    for (int k = 0; k < 4; k++){
        int tau = t - 3 + k;
        if (tau >= 0){
            int src = REV ? (LL-1-tau) : tau;
            s += w[k] * g_xz[(size_t)(n*LL + src)*(2*DI) + d];
        }
    }
    g_xc[(size_t)m*DI + d] = siluf(s);
}

// ---------------- selective scan: 4 states/thread, shfl-reduce over state group ------
template<int ADDFLIP>
__global__ void k_scan(const float* __restrict__ Alog, const float* __restrict__ Dp,
                       float* __restrict__ y){
    int n  = blockIdx.y;
    int ch = blockIdx.x*64 + (threadIdx.x >> 2);  // (16,16) x 256
    int s0 = (threadIdx.x & 3) * 4;
    float A2[4];
    #pragma unroll
    for (int i = 0; i < 4; i++)
        A2[i] = -__expf(Alog[ch*DS + s0 + i]) * 1.44269504088896f;  // A*log2(e)
    float Dv = Dp[ch];
    float h0=0.f,h1=0.f,h2=0.f,h3=0.f;
    size_t base = (size_t)n*LL;

    float u  = g_xc[(base)*DI + ch];
    float dv = g_dt[(base)*DI + ch];
    float4 Bv = *(const float4*)&g_dbl[(base)*64 + DTR + s0];
    float4 Cv = *(const float4*)&g_dbl[(base)*64 + DTR + DS + s0];

    for (int t = 0; t < LL; t++){
        float un = 0.f, dn = 0.f;
        float4 Bn = make_float4(0,0,0,0), Cn = make_float4(0,0,0,0);
        if (t + 1 < LL){
            size_t r = base + t + 1;
            un = g_xc[r*DI + ch];
            dn = g_dt[r*DI + ch];
            Bn = *(const float4*)&g_dbl[r*64 + DTR + s0];
            Cn = *(const float4*)&g_dbl[r*64 + DTR + DS + s0];
        }
        float du = dv*u;
        h0 = exp2f(dv*A2[0])*h0 + du*Bv.x;
        h1 = exp2f(dv*A2[1])*h1 + du*Bv.y;
        h2 = exp2f(dv*A2[2])*h2 + du*Bv.z;
        h3 = exp2f(dv*A2[3])*h3 + du*Bv.w;
        float acc = h0*Cv.x + h1*Cv.y + h2*Cv.z + h3*Cv.w;
        acc += __shfl_xor_sync(0xffffffffu, acc, 1);
        acc += __shfl_xor_sync(0xffffffffu, acc, 2);
        if ((threadIdx.x & 3) == 0){
            int tout = ADDFLIP ? (LL-1-t) : t;
            float val = acc + u*Dv;
            float* py = &y[(base + tout)*DI + ch];
            if (ADDFLIP) *py += val; else *py = val;
        }
        u = un; dv = dn; Bv = Bn; Cv = Cn;
    }
}

// ---------------- ys = (y_f + y_b) * silu(z), into g_xc (reuse) ----------------
__global__ void k_ymul(){
    size_t m = blockIdx.x; int d = threadIdx.x;   // 8192 x 1024
    float z = g_xz[m*(2*DI) + DI + d];
    g_xc[m*DI + d] = g_y[m*DI + d] * siluf(z);
}

// ---------------- final: out = mm*(1+0.1dA) + 0.1dC + res_w*residual; h_final -------
__global__ void k_final(const float* __restrict__ resid, float* __restrict__ out,
                        float* __restrict__ hfin, const float* __restrict__ resw){
    int m = blockIdx.x, j = threadIdx.x;   // 8192 x 512
    int n = m >> 9, t = m & 511;
    float v = g_hn[(size_t)m*DM + j];
    v = v*(1.0f + 0.1f*g_dA[n*DM + j]) + 0.1f*g_dC[n*DM + j]
        + resw[0]*resid[(size_t)m*DM + j];
    out[(size_t)m*DM + j] = v;
    if (t == LL-1) hfin[n*DM + j] = v;
}

// ---------------- launch ----------------
extern "C" void kernel_launch(void* const* d_in, const int* in_sizes, int n_in,
                              void* d_out, int out_size)
{
    const float* x      = (const float*)d_in[0];
    const int*   sid    = (const int*)  d_in[1];
    const float* h_init = (const float*)d_in[2];
    const float* W_gf   = (const float*)d_in[3];
    const float* b_gf   = (const float*)d_in[4];
    const float* emb    = (const float*)d_in[5];
    const float* W1     = (const float*)d_in[6];
    const float* b1     = (const float*)d_in[7];
    const float* W2     = (const float*)d_in[8];
    const float* b2     = (const float*)d_in[9];
    const float* W3     = (const float*)d_in[10];
    const float* b3     = (const float*)d_in[11];
    const float* ln_g   = (const float*)d_in[12];
    const float* ln_b   = (const float*)d_in[13];
    const float* rms_w  = (const float*)d_in[14];
    const float* W_in   = (const float*)d_in[15];
    const float* W_out  = (const float*)d_in[16];
    const float* res_w  = (const float*)d_in[17];
    const float* convw_f= (const float*)d_in[18];
    const float* convb_f= (const float*)d_in[19];
    const float* xproj_f= (const float*)d_in[20];
    const float* dtw_f  = (const float*)d_in[21];
    const float* dtb_f  = (const float*)d_in[22];
    const float* Alog_f = (const float*)d_in[23];
    const float* D_f    = (const float*)d_in[24];
    const float* convw_b= (const float*)d_in[25];
    const float* convb_b= (const float*)d_in[26];
    const float* xproj_b= (const float*)d_in[27];
    const float* dtw_b  = (const float*)d_in[28];
    const float* dtb_b  = (const float*)d_in[29];
    const float* Alog_b = (const float*)d_in[30];
    const float* D_b    = (const float*)d_in[31];

    float* out   = (float*)d_out;
    float* resid = out + (size_t)ROWS*DM;
    float* hfin  = out + 2*(size_t)ROWS*DM;

    float *p_hn, *p_xz, *p_xc, *p_dbl, *p_dt, *p_y;
    cudaGetSymbolAddress((void**)&p_hn,  g_hn);
    cudaGetSymbolAddress((void**)&p_xz,  g_xz);
    cudaGetSymbolAddress((void**)&p_xc,  g_xc);
    cudaGetSymbolAddress((void**)&p_dbl, g_dbl);
    cudaGetSymbolAddress((void**)&p_dt,  g_dt);
    cudaGetSymbolAddress((void**)&p_y,   g_y);

    // conditioning path
    k_mean<<<NB, DM>>>(x);
    k_gf<<<NB, 128>>>(W_gf, b_gf);
    k_h1<<<NB, DM>>>(W1, b1, emb, sid);
    k_h2<<<NB, DM>>>(W2, b2);
    k_off<<<dim3(NB,3), DM>>>(W3, b3, ln_g, ln_b, sid);

    // residual + rmsnorm
    k_res<<<ROWS, DM>>>(x, h_init, rms_w, resid);

    // xz = hn @ W_in.T   (8192 x 2048, K=512)
    gemm_nt<128,128,8,8,8,0><<<dim3(2*DI/128, ROWS/128), 256>>>(
        p_hn, DM, W_in, DM, p_xz, 2*DI, DM, nullptr);

    // forward direction
    k_conv<0><<<dim3(ROWS,4), 256>>>(convw_f, convb_f);
    gemm_nt<64,64,8,4,4,0><<<dim3(1, ROWS/64), 256>>>(
        p_xc, DI, xproj_f, DI, p_dbl, 64, DI, nullptr);
    gemm_nt<128,128,8,8,8,1><<<dim3(DI/128, ROWS/128), 256>>>(
        p_dbl, 64, dtw_f, DTR, p_dt, DI, DTR, dtb_f);
    k_scan<0><<<dim3(16, NB), 256>>>(Alog_f, D_f, p_y);

    // backward direction (flip handled inside conv + scan-store)
    k_conv<1><<<dim3(ROWS,4), 256>>>(convw_b, convb_b);
    gemm_nt<64,64,8,4,4,0><<<dim3(1, ROWS/64), 256>>>(
        p_xc, DI, xproj_b, DI, p_dbl, 64, DI, nullptr);
    gemm_nt<128,128,8,8,8,1><<<dim3(DI/128, ROWS/128), 256>>>(
        p_dbl, 64, dtw_b, DTR, p_dt, DI, DTR, dtb_b);
    k_scan<1><<<dim3(16, NB), 256>>>(Alog_b, D_b, p_y);

    // gating + output projection
    k_ymul<<<ROWS, DI>>>();
    gemm_nt<128,128,8,8,8,0><<<dim3(DM/128, ROWS/128), 256>>>(
        p_xc, DI, W_out, DI, p_hn, DM, DI, nullptr);

    // final epilogue
    k_final<<<ROWS, DM>>>(resid, out, hfin, res_w);
}

// round 3
// speedup vs baseline: 1.9524x; 1.9524x over previous
#include <cuda_runtime.h>
#include <math.h>

#define NB   16
#define LL   512
#define DM   512
#define DI   1024
#define DS   16
#define DTR  32
#define ROWS (NB*LL)   // 8192

// ---------------- scratch (static device globals; no allocation) ----------------
__device__ float g_xmean_part[8][NB*DM];
__device__ float g_gf[NB*128];
__device__ float g_h1[NB*DM];
__device__ float g_h2[NB*DM];
__device__ float g_off[NB*3*DM];
__device__ float g_dA[NB*DM];
__device__ float g_dB[NB*DM];
__device__ float g_dC[NB*DM];
__device__ float g_hn[ROWS*DM];        // rmsnorm output; later reused for out_mm
__device__ float g_xz[ROWS*2*DI];      // W_in output: cols [0,1024)=xs_, [1024,2048)=z
__device__ float g_xc[ROWS*DI];        // conv+silu output; later reused for ys
__device__ float g_dbl[ROWS*64];       // xproj output: [0,32)=dtraw, [32,48)=B, [48,64)=C
__device__ float g_dt[ROWS*DI];        // softplus(dt)
__device__ float g_y[ROWS*DI];         // scan output accumulator

// ---------------- helpers ----------------
__device__ __forceinline__ float geluf(float x){
    return 0.5f*x*(1.0f + erff(x*0.70710678118654752f));
}
__device__ __forceinline__ float siluf(float x){
    return x / (1.0f + __expf(-x));
}
__device__ __forceinline__ float softplusf(float x){
    return (x > 20.0f) ? x : log1pf(__expf(x));
}
__device__ __forceinline__ unsigned f2tf(float x){
    unsigned r; asm("cvt.rna.tf32.f32 %0, %1;" : "=r"(r) : "f"(x)); return r;
}
__device__ __forceinline__ void mma_tf32(float* d, const unsigned* a, const unsigned* b){
    asm volatile("mma.sync.aligned.m16n8k8.row.col.f32.tf32.tf32.f32 "
        "{%0,%1,%2,%3}, {%4,%5,%6,%7}, {%8,%9}, {%0,%1,%2,%3};"
        : "+f"(d[0]), "+f"(d[1]), "+f"(d[2]), "+f"(d[3])
        : "r"(a[0]), "r"(a[1]), "r"(a[2]), "r"(a[3]), "r"(b[0]), "r"(b[1]));
}
// warp dot over K (K multiple of 128), w/ sx 16B aligned
__device__ __forceinline__ float warp_dot(const float* __restrict__ w,
                                          const float* __restrict__ sx, int K, int lane){
    float s = 0.f;
    for (int k = lane*4; k < K; k += 128){
        float4 a = *(const float4*)&w[k];
        float4 b = *(const float4*)&sx[k];
        s += a.x*b.x + a.y*b.y + a.z*b.z + a.w*b.w;
    }
    #pragma unroll
    for (int o = 16; o; o >>= 1) s += __shfl_xor_sync(0xffffffffu, s, o);
    return s;
}

// ---------------- K1: partial mean over L (phase 1) ----------------
__global__ void k_meanp(const float* __restrict__ x){
    int n = blockIdx.x, p = blockIdx.y, j = threadIdx.x;   // (16,8) x 512
    const float* px = x + ((size_t)n*LL + p*64)*DM + j;
    float s = 0.f;
    #pragma unroll 8
    for (int t = 0; t < 64; t++) s += px[(size_t)t*DM];
    g_xmean_part[p][n*DM + j] = s;
}

// ---------------- K2a: gf = gelu(xmean @ W_gf.T + b_gf), warp per output ----------
__global__ void __launch_bounds__(256) k_gf(const float* __restrict__ Wgf,
                                            const float* __restrict__ bgf){
    __shared__ __align__(16) float sx[DM];
    int n = blockIdx.x, tid = threadIdx.x;                 // (16,16) x 256
    for (int k = tid; k < DM; k += 256){
        float s = 0.f;
        #pragma unroll
        for (int p = 0; p < 8; p++) s += g_xmean_part[p][n*DM + k];
        sx[k] = s * (1.0f/LL);
    }
    __syncthreads();
    int wid = tid >> 5, lane = tid & 31;
    int j = blockIdx.y*8 + wid;                            // 128 outputs
    float s = warp_dot(Wgf + (size_t)j*DM, sx, DM, lane);
    if (lane == 0) g_gf[n*128 + j] = geluf(s + bgf[j]);
}

// ---------------- K2b: h1 = gelu([gf, emb[sid]] @ W1.T + b1) ----------------
__global__ void __launch_bounds__(256) k_h1(const float* __restrict__ W1,
                                            const float* __restrict__ b1,
                                            const float* __restrict__ emb,
                                            const int* __restrict__ sid){
    __shared__ __align__(16) float sc[256];
    int n = blockIdx.x, tid = threadIdx.x;                 // (16,64) x 256
    if (tid < 128) sc[tid] = g_gf[n*128 + tid];
    else sc[tid] = emb[sid[0]*128 + (tid-128)];
    __syncthreads();
    int wid = tid >> 5, lane = tid & 31;
    int j = blockIdx.y*8 + wid;                            // 512 outputs
    float s = warp_dot(W1 + (size_t)j*256, sc, 256, lane);
    if (lane == 0) g_h1[n*DM + j] = geluf(s + b1[j]);
}

// ---------------- K2c: h2 = gelu(h1 @ W2.T + b2) ----------------
__global__ void __launch_bounds__(256) k_h2(const float* __restrict__ W2,
                                            const float* __restrict__ b2){
    __shared__ __align__(16) float sh[DM];
    int n = blockIdx.x, tid = threadIdx.x;                 // (16,64) x 256
    for (int k = tid; k < DM; k += 256) sh[k] = g_h1[n*DM + k];
    __syncthreads();
    int wid = tid >> 5, lane = tid & 31;
    int j = blockIdx.y*8 + wid;
    float s = warp_dot(W2 + (size_t)j*DM, sh, DM, lane);
    if (lane == 0) g_h2[n*DM + j] = geluf(s + b2[j]);
}

// ---------------- K2d-1: off = h2 @ W3.T + b3 (raw) ----------------
__global__ void __launch_bounds__(256) k_offmm(const float* __restrict__ W3,
                                               const float* __restrict__ b3){
    __shared__ __align__(16) float sh[DM];
    int n = blockIdx.x, tid = threadIdx.x;                 // (16,192) x 256
    for (int k = tid; k < DM; k += 256) sh[k] = g_h2[n*DM + k];
    __syncthreads();
    int wid = tid >> 5, lane = tid & 31;
    int j = blockIdx.y*8 + wid;                            // 1536 outputs
    float s = warp_dot(W3 + (size_t)j*DM, sh, DM, lane);
    if (lane == 0) g_off[n*1536 + j] = s + b3[j];
}

// ---------------- K2d-2: per-chunk LayerNorm -> dA*sc, dB, dC ----------------
__global__ void k_offln(const float* __restrict__ lng, const float* __restrict__ lnb,
                        const int* __restrict__ sid){
    __shared__ float r1[16], r2[16];
    int n = blockIdx.x, c = blockIdx.y, j = threadIdx.x;   // (16,3) x 512
    float s = g_off[n*1536 + c*DM + j];
    float s1 = s, s2 = s*s;
    #pragma unroll
    for (int o = 16; o > 0; o >>= 1){
        s1 += __shfl_xor_sync(0xffffffffu, s1, o);
        s2 += __shfl_xor_sync(0xffffffffu, s2, o);
    }
    int wid = j >> 5, ln = j & 31;
    if (ln == 0){ r1[wid] = s1; r2[wid] = s2; }
    __syncthreads();
    if (j < 16){
        float a = r1[j], b = r2[j];
        #pragma unroll
        for (int o = 8; o > 0; o >>= 1){
            a += __shfl_xor_sync(0x0000ffffu, a, o);
            b += __shfl_xor_sync(0x0000ffffu, b, o);
        }
        if (j == 0){ r1[0] = a; r2[0] = b; }
    }
    __syncthreads();
    float mu  = r1[0] * (1.0f/DM);
    float var = r2[0] * (1.0f/DM) - mu*mu;
    float v = (s - mu) * rsqrtf(var + 1e-5f) * lng[j] + lnb[j];
    if (c == 0){
        float scv = 0.9f - 0.3f*(float)sid[0];
        g_dA[n*DM + j] = v * scv;
    } else if (c == 1) g_dB[n*DM + j] = v;
    else               g_dC[n*DM + j] = v;
}

// ---------------- K3: residual = x + dB (+h_init at t=0); hn = rmsnorm(residual) ----
__global__ void k_res(const float* __restrict__ x, const float* __restrict__ hinit,
                      const float* __restrict__ rmsw, float* __restrict__ resid){
    __shared__ float red[16];
    int m = blockIdx.x, j = threadIdx.x;     // 8192 x 512
    int n = m >> 9, t = m & 511;
    float v = x[(size_t)m*DM + j] + g_dB[n*DM + j];
    if (t == 0) v += hinit[n*DM + j];
    resid[(size_t)m*DM + j] = v;
    float s2 = v*v;
    #pragma unroll
    for (int o = 16; o > 0; o >>= 1) s2 += __shfl_xor_sync(0xffffffffu, s2, o);
    int wid = j >> 5, ln = j & 31;
    if (ln == 0) red[wid] = s2;
    __syncthreads();
    if (j < 16){
        float a = red[j];
        #pragma unroll
        for (int o = 8; o > 0; o >>= 1) a += __shfl_xor_sync(0x0000ffffu, a, o);
        if (j == 0) red[0] = a;
    }
    __syncthreads();
    float rs = rsqrtf(red[0]*(1.0f/DM) + 1e-5f);
    g_hn[(size_t)m*DM + j] = v * rs * rmsw[j];
}

// ---------------- tf32 tensor-core GEMM: C[M,N] = A[M,K] * B[N,K]^T ----------------
// 8 warps, warp grid WGM x WGN (WGM*WGN==8). EPI==1: C = softplus(C + bias[col]).
template<int BM,int BN,int WGM,int WGN,int EPI>
__global__ void __launch_bounds__(256) gemm_tf32(
    const float* __restrict__ A, int lda,
    const float* __restrict__ B, int ldb,
    float* __restrict__ C, int ldc,
    int K, const float* __restrict__ bias)
{
    constexpr int WM = BM/WGM, WN = BN/WGN;
    constexpr int MF = WM/16, NF = WN/8;
    __shared__ unsigned sA[BM*20];
    __shared__ unsigned sB[BN*20];
    int tid = threadIdx.x;
    int lane = tid & 31, wid = tid >> 5;
    int wm = wid % WGM, wn = wid / WGM;
    int bm0 = blockIdx.y*BM, bn0 = blockIdx.x*BN;

    float acc[MF][NF][4];
    #pragma unroll
    for (int i = 0; i < MF; i++)
        #pragma unroll
        for (int j = 0; j < NF; j++)
            #pragma unroll
            for (int r = 0; r < 4; r++) acc[i][j][r] = 0.f;

    for (int k0 = 0; k0 < K; k0 += 16){
        #pragma unroll
        for (int i = tid*4; i < BM*16; i += 256*4){
            int r = i >> 4, c = i & 15;
            float4 v = *(const float4*)&A[(size_t)(bm0+r)*lda + k0 + c];
            sA[r*20+c  ] = f2tf(v.x); sA[r*20+c+1] = f2tf(v.y);
            sA[r*20+c+2] = f2tf(v.z); sA[r*20+c+3] = f2tf(v.w);
        }
        #pragma unroll
        for (int i = tid*4; i < BN*16; i += 256*4){
            int r = i >> 4, c = i & 15;
            float4 v = *(const float4*)&B[(size_t)(bn0+r)*ldb + k0 + c];
            sB[r*20+c  ] = f2tf(v.x); sB[r*20+c+1] = f2tf(v.y);
            sB[r*20+c+2] = f2tf(v.z); sB[r*20+c+3] = f2tf(v.w);
        }
        __syncthreads();
        #pragma unroll
        for (int kk = 0; kk < 16; kk += 8){
            unsigned af[MF][4], bf[NF][2];
            int c = kk + (lane & 3);
            #pragma unroll
            for (int mf = 0; mf < MF; mf++){
                int r = wm*WM + mf*16 + (lane >> 2);
                af[mf][0] = sA[r*20 + c];
                af[mf][1] = sA[(r+8)*20 + c];
                af[mf][2] = sA[r*20 + c + 4];
                af[mf][3] = sA[(r+8)*20 + c + 4];
            }
            #pragma unroll
            for (int nf = 0; nf < NF; nf++){
                int nr = wn*WN + nf*8 + (lane >> 2);
                bf[nf][0] = sB[nr*20 + c];
                bf[nf][1] = sB[nr*20 + c + 4];
            }
            #pragma unroll
            for (int mf = 0; mf < MF; mf++)
                #pragma unroll
                for (int nf = 0; nf < NF; nf++)
                    mma_tf32(acc[mf][nf], af[mf], bf[nf]);
        }
        __syncthreads();
    }
    #pragma unroll
    for (int mf = 0; mf < MF; mf++){
        int row0 = bm0 + wm*WM + mf*16 + (lane >> 2);
        #pragma unroll
        for (int nf = 0; nf < NF; nf++){
            int col = bn0 + wn*WN + nf*8 + (lane & 3)*2;
            float v0 = acc[mf][nf][0], v1 = acc[mf][nf][1];
            float v2 = acc[mf][nf][2], v3 = acc[mf][nf][3];
            if (EPI == 1){
                float bA = bias[col], bB = bias[col+1];
                v0 = softplusf(v0 + bA); v1 = softplusf(v1 + bB);
                v2 = softplusf(v2 + bA); v3 = softplusf(v3 + bB);
            }
            *(float2*)&C[(size_t)row0*ldc + col]     = make_float2(v0, v1);
            *(float2*)&C[(size_t)(row0+8)*ldc + col] = make_float2(v2, v3);
        }
    }
}

// ---------------- depthwise causal conv + silu (REV handles sequence flip) ----------
template<int REV>
__global__ void k_conv(const float* __restrict__ cw, const float* __restrict__ cb){
    int m = blockIdx.x;                     // scan-time position n*512+t
    int n = m >> 9, t = m & 511;
    int d = blockIdx.y*256 + threadIdx.x;   // (8192,4) x 256
    const float* w = cw + d*4;
    float s = cb[d];
    #pragma unroll
    for (int k = 0; k < 4; k++){
        int tau = t - 3 + k;
        if (tau >= 0){
            int src = REV ? (LL-1-tau) : tau;
            s += w[k] * g_xz[(size_t)(n*LL + src)*(2*DI) + d];
        }
    }
    g_xc[(size_t)m*DI + d] = siluf(s);
}

// ---------------- selective scan: 4 states/thread, shfl-reduce over state group ------
template<int ADDFLIP>
__global__ void k_scan(const float* __restrict__ Alog, const float* __restrict__ Dp,
                       float* __restrict__ y){
    int n  = blockIdx.y;
    int ch = blockIdx.x*64 + (threadIdx.x >> 2);  // (16,16) x 256
    int s0 = (threadIdx.x & 3) * 4;
    float A2[4];
    #pragma unroll
    for (int i = 0; i < 4; i++)
        A2[i] = -__expf(Alog[ch*DS + s0 + i]) * 1.44269504088896f;  // A*log2(e)
    float Dv = Dp[ch];
    float h0=0.f,h1=0.f,h2=0.f,h3=0.f;
    size_t base = (size_t)n*LL;

    float u  = g_xc[(base)*DI + ch];
    float dv = g_dt[(base)*DI + ch];
    float4 Bv = *(const float4*)&g_dbl[(base)*64 + DTR + s0];
    float4 Cv = *(const float4*)&g_dbl[(base)*64 + DTR + DS + s0];

    for (int t = 0; t < LL; t++){
        float un = 0.f, dn = 0.f;
        float4 Bn = make_float4(0,0,0,0), Cn = make_float4(0,0,0,0);
        if (t + 1 < LL){
            size_t r = base + t + 1;
            un = g_xc[r*DI + ch];
            dn = g_dt[r*DI + ch];
            Bn = *(const float4*)&g_dbl[r*64 + DTR + s0];
            Cn = *(const float4*)&g_dbl[r*64 + DTR + DS + s0];
        }
        float du = dv*u;
        h0 = exp2f(dv*A2[0])*h0 + du*Bv.x;
        h1 = exp2f(dv*A2[1])*h1 + du*Bv.y;
        h2 = exp2f(dv*A2[2])*h2 + du*Bv.z;
        h3 = exp2f(dv*A2[3])*h3 + du*Bv.w;
        float acc = h0*Cv.x + h1*Cv.y + h2*Cv.z + h3*Cv.w;
        acc += __shfl_xor_sync(0xffffffffu, acc, 1);
        acc += __shfl_xor_sync(0xffffffffu, acc, 2);
        if ((threadIdx.x & 3) == 0){
            int tout = ADDFLIP ? (LL-1-t) : t;
            float val = acc + u*Dv;
            float* py = &y[(base + tout)*DI + ch];
            if (ADDFLIP) *py += val; else *py = val;
        }
        u = un; dv = dn; Bv = Bn; Cv = Cn;
    }
}

// ---------------- ys = (y_f + y_b) * silu(z), into g_xc (reuse) ----------------
__global__ void k_ymul(){
    size_t m = blockIdx.x; int d = threadIdx.x;   // 8192 x 1024
    float z = g_xz[m*(2*DI) + DI + d];
    g_xc[m*DI + d] = g_y[m*DI + d] * siluf(z);
}

// ---------------- final: out = mm*(1+0.1dA) + 0.1dC + res_w*residual; h_final -------
__global__ void k_final(const float* __restrict__ resid, float* __restrict__ out,
                        float* __restrict__ hfin, const float* __restrict__ resw){
    int m = blockIdx.x, j = threadIdx.x;   // 8192 x 512
    int n = m >> 9, t = m & 511;
    float v = g_hn[(size_t)m*DM + j];
    v = v*(1.0f + 0.1f*g_dA[n*DM + j]) + 0.1f*g_dC[n*DM + j]
        + resw[0]*resid[(size_t)m*DM + j];
    out[(size_t)m*DM + j] = v;
    if (t == LL-1) hfin[n*DM + j] = v;
}

// ---------------- launch ----------------
extern "C" void kernel_launch(void* const* d_in, const int* in_sizes, int n_in,
                              void* d_out, int out_size)
{
    const float* x      = (const float*)d_in[0];
    const int*   sid    = (const int*)  d_in[1];
    const float* h_init = (const float*)d_in[2];
    const float* W_gf   = (const float*)d_in[3];
    const float* b_gf   = (const float*)d_in[4];
    const float* emb    = (const float*)d_in[5];
    const float* W1     = (const float*)d_in[6];
    const float* b1     = (const float*)d_in[7];
    const float* W2     = (const float*)d_in[8];
    const float* b2     = (const float*)d_in[9];
    const float* W3     = (const float*)d_in[10];
    const float* b3     = (const float*)d_in[11];
    const float* ln_g   = (const float*)d_in[12];
    const float* ln_b   = (const float*)d_in[13];
    const float* rms_w  = (const float*)d_in[14];
    const float* W_in   = (const float*)d_in[15];
    const float* W_out  = (const float*)d_in[16];
    const float* res_w  = (const float*)d_in[17];
    const float* convw_f= (const float*)d_in[18];
    const float* convb_f= (const float*)d_in[19];
    const float* xproj_f= (const float*)d_in[20];
    const float* dtw_f  = (const float*)d_in[21];
    const float* dtb_f  = (const float*)d_in[22];
    const float* Alog_f = (const float*)d_in[23];
    const float* D_f    = (const float*)d_in[24];
    const float* convw_b= (const float*)d_in[25];
    const float* convb_b= (const float*)d_in[26];
    const float* xproj_b= (const float*)d_in[27];
    const float* dtw_b  = (const float*)d_in[28];
    const float* dtb_b  = (const float*)d_in[29];
    const float* Alog_b = (const float*)d_in[30];
    const float* D_b    = (const float*)d_in[31];

    float* out   = (float*)d_out;
    float* resid = out + (size_t)ROWS*DM;
    float* hfin  = out + 2*(size_t)ROWS*DM;

    float *p_hn, *p_xz, *p_xc, *p_dbl, *p_dt, *p_y;
    cudaGetSymbolAddress((void**)&p_hn,  g_hn);
    cudaGetSymbolAddress((void**)&p_xz,  g_xz);
    cudaGetSymbolAddress((void**)&p_xc,  g_xc);
    cudaGetSymbolAddress((void**)&p_dbl, g_dbl);
    cudaGetSymbolAddress((void**)&p_dt,  g_dt);
    cudaGetSymbolAddress((void**)&p_y,   g_y);

    // conditioning path (warp-per-output GEMV style)
    k_meanp<<<dim3(NB,8), DM>>>(x);
    k_gf<<<dim3(NB,16), 256>>>(W_gf, b_gf);
    k_h1<<<dim3(NB,64), 256>>>(W1, b1, emb, sid);
    k_h2<<<dim3(NB,64), 256>>>(W2, b2);
    k_offmm<<<dim3(NB,192), 256>>>(W3, b3);
    k_offln<<<dim3(NB,3), DM>>>(ln_g, ln_b, sid);

    // residual + rmsnorm
    k_res<<<ROWS, DM>>>(x, h_init, rms_w, resid);

    // xz = hn @ W_in.T   (8192 x 2048, K=512), tf32 tensor cores
    gemm_tf32<128,128,2,4,0><<<dim3(16, 64), 256>>>(
        p_hn, DM, W_in, DM, p_xz, 2*DI, DM, nullptr);

    // forward direction
    k_conv<0><<<dim3(ROWS,4), 256>>>(convw_f, convb_f);
    gemm_tf32<128,64,4,2,0><<<dim3(1, 64), 256>>>(
        p_xc, DI, xproj_f, DI, p_dbl, 64, DI, nullptr);
    gemm_tf32<128,128,2,4,1><<<dim3(8, 64), 256>>>(
        p_dbl, 64, dtw_f, DTR, p_dt, DI, DTR, dtb_f);
    k_scan<0><<<dim3(16, NB), 256>>>(Alog_f, D_f, p_y);

    // backward direction (flip handled inside conv + scan-store)
    k_conv<1><<<dim3(ROWS,4), 256>>>(convw_b, convb_b);
    gemm_tf32<128,64,4,2,0><<<dim3(1, 64), 256>>>(
        p_xc, DI, xproj_b, DI, p_dbl, 64, DI, nullptr);
    gemm_tf32<128,128,2,4,1><<<dim3(8, 64), 256>>>(
        p_dbl, 64, dtw_b, DTR, p_dt, DI, DTR, dtb_b);
    k_scan<1><<<dim3(16, NB), 256>>>(Alog_b, D_b, p_y);

    // gating + output projection
    k_ymul<<<ROWS, DI>>>();
    gemm_tf32<128,128,2,4,0><<<dim3(4, 64), 256>>>(
        p_xc, DI, W_out, DI, p_hn, DM, DI, nullptr);

    // final epilogue
    k_final<<<ROWS, DM>>>(resid, out, hfin, res_w);
}

// round 4
// speedup vs baseline: 2.7549x; 1.4111x over previous
#include <cuda_runtime.h>
#include <cuda_bf16.h>
#include <math.h>

#define NB   16
#define LL   512
#define DM   512
#define DI   1024
#define DS   16
#define DTR  32
#define ROWS (NB*LL)   // 8192

// ---------------- scratch (static device globals; no allocation) ----------------
__device__ float g_xmean_part[8][NB*DM];
__device__ float g_gf[NB*128];
__device__ float g_h1[NB*DM];
__device__ float g_h2[NB*DM];
__device__ float g_off[NB*3*DM];
__device__ float g_dA[NB*DM];
__device__ float g_dB[NB*DM];
__device__ float g_dC[NB*DM];
__device__ float g_xz[ROWS*2*DI];      // W_in output fp32: [0,1024)=xs_, [1024,2048)=z
__device__ float g_xc[ROWS*DI];        // conv+silu output fp32 (scan u)
__device__ float g_dbl[ROWS*64];       // xproj out fp32: [0,32)=dtraw, [32,48)=B, [48,64)=C
__device__ float g_dt[ROWS*DI];        // softplus dt fp32
__device__ float g_y[ROWS*DI];         // scan output accumulator fp32
__device__ __align__(16) __nv_bfloat16 g_hnb[ROWS*DM];   // rmsnorm out bf16 (A of W_in gemm)
__device__ __align__(16) __nv_bfloat16 g_xcb[ROWS*DI];   // conv out bf16 / ymul out bf16
__device__ __align__(16) __nv_bfloat16 g_dblb[ROWS*DTR]; // dtraw bf16 (A of dt gemm)
__device__ __align__(16) __nv_bfloat16 g_wb[1769472];    // converted weights

// weight offsets in g_wb
#define OFF_WIN   0
#define OFF_WOUT  1048576
#define OFF_XPF   1572864
#define OFF_XPB   1638400
#define OFF_DTWF  1703936
#define OFF_DTWB  1736704

// ---------------- helpers ----------------
__device__ __forceinline__ float geluf(float x){
    return 0.5f*x*(1.0f + erff(x*0.70710678118654752f));
}
__device__ __forceinline__ float siluf(float x){
    return x / (1.0f + __expf(-x));
}
__device__ __forceinline__ float softplusf(float x){
    return (x > 20.0f) ? x : log1pf(__expf(x));
}
__device__ __forceinline__ void mma_bf16(float* d, const unsigned* a, const unsigned* b){
    asm volatile("mma.sync.aligned.m16n8k16.row.col.f32.bf16.bf16.f32 "
        "{%0,%1,%2,%3}, {%4,%5,%6,%7}, {%8,%9}, {%0,%1,%2,%3};"
        : "+f"(d[0]), "+f"(d[1]), "+f"(d[2]), "+f"(d[3])
        : "r"(a[0]), "r"(a[1]), "r"(a[2]), "r"(a[3]), "r"(b[0]), "r"(b[1]));
}
__device__ __forceinline__ float warp_dot(const float* __restrict__ w,
                                          const float* __restrict__ sx, int K, int lane){
    float s = 0.f;
    for (int k = lane*4; k < K; k += 128){
        float4 a = *(const float4*)&w[k];
        float4 b = *(const float4*)&sx[k];
        s += a.x*b.x + a.y*b.y + a.z*b.z + a.w*b.w;
    }
    #pragma unroll
    for (int o = 16; o; o >>= 1) s += __shfl_xor_sync(0xffffffffu, s, o);
    return s;
}

// ---------------- weight fp32->bf16 convert ----------------
__global__ void k_cvt(const float* __restrict__ s, __nv_bfloat16* __restrict__ d, int n){
    int i = blockIdx.x*256 + threadIdx.x;
    if (i < n) d[i] = __float2bfloat16(s[i]);
}

// ---------------- K1: partial mean over L ----------------
__global__ void k_meanp(const float* __restrict__ x){
    int n = blockIdx.x, p = blockIdx.y, j = threadIdx.x;   // (16,8) x 512
    const float* px = x + ((size_t)n*LL + p*64)*DM + j;
    float s = 0.f;
    #pragma unroll 8
    for (int t = 0; t < 64; t++) s += px[(size_t)t*DM];
    g_xmean_part[p][n*DM + j] = s;
}

// ---------------- conditioning GEMVs (warp per output) ----------------
__global__ void __launch_bounds__(256) k_gf(const float* __restrict__ Wgf,
                                            const float* __restrict__ bgf){
    __shared__ __align__(16) float sx[DM];
    int n = blockIdx.x, tid = threadIdx.x;                 // (16,16) x 256
    for (int k = tid; k < DM; k += 256){
        float s = 0.f;
        #pragma unroll
        for (int p = 0; p < 8; p++) s += g_xmean_part[p][n*DM + k];
        sx[k] = s * (1.0f/LL);
    }
    __syncthreads();
    int wid = tid >> 5, lane = tid & 31;
    int j = blockIdx.y*8 + wid;
    float s = warp_dot(Wgf + (size_t)j*DM, sx, DM, lane);
    if (lane == 0) g_gf[n*128 + j] = geluf(s + bgf[j]);
}

__global__ void __launch_bounds__(256) k_h1(const float* __restrict__ W1,
                                            const float* __restrict__ b1,
                                            const float* __restrict__ emb,
                                            const int* __restrict__ sid){
    __shared__ __align__(16) float sc[256];
    int n = blockIdx.x, tid = threadIdx.x;                 // (16,64) x 256
    if (tid < 128) sc[tid] = g_gf[n*128 + tid];
    else sc[tid] = emb[sid[0]*128 + (tid-128)];
    __syncthreads();
    int wid = tid >> 5, lane = tid & 31;
    int j = blockIdx.y*8 + wid;
    float s = warp_dot(W1 + (size_t)j*256, sc, 256, lane);
    if (lane == 0) g_h1[n*DM + j] = geluf(s + b1[j]);
}

__global__ void __launch_bounds__(256) k_h2(const float* __restrict__ W2,
                                            const float* __restrict__ b2){
    __shared__ __align__(16) float sh[DM];
    int n = blockIdx.x, tid = threadIdx.x;                 // (16,64) x 256
    for (int k = tid; k < DM; k += 256) sh[k] = g_h1[n*DM + k];
    __syncthreads();
    int wid = tid >> 5, lane = tid & 31;
    int j = blockIdx.y*8 + wid;
    float s = warp_dot(W2 + (size_t)j*DM, sh, DM, lane);
    if (lane == 0) g_h2[n*DM + j] = geluf(s + b2[j]);
}

__global__ void __launch_bounds__(256) k_offmm(const float* __restrict__ W3,
                                               const float* __restrict__ b3){
    __shared__ __align__(16) float sh[DM];
    int n = blockIdx.x, tid = threadIdx.x;                 // (16,192) x 256
    for (int k = tid; k < DM; k += 256) sh[k] = g_h2[n*DM + k];
    __syncthreads();
    int wid = tid >> 5, lane = tid & 31;
    int j = blockIdx.y*8 + wid;
    float s = warp_dot(W3 + (size_t)j*DM, sh, DM, lane);
    if (lane == 0) g_off[n*1536 + j] = s + b3[j];
}

__global__ void k_offln(const float* __restrict__ lng, const float* __restrict__ lnb,
                        const int* __restrict__ sid){
    __shared__ float r1[16], r2[16];
    int n = blockIdx.x, c = blockIdx.y, j = threadIdx.x;   // (16,3) x 512
    float s = g_off[n*1536 + c*DM + j];
    float s1 = s, s2 = s*s;
    #pragma unroll
    for (int o = 16; o > 0; o >>= 1){
        s1 += __shfl_xor_sync(0xffffffffu, s1, o);
        s2 += __shfl_xor_sync(0xffffffffu, s2, o);
    }
    int wid = j >> 5, ln = j & 31;
    if (ln == 0){ r1[wid] = s1; r2[wid] = s2; }
    __syncthreads();
    if (j < 16){
        float a = r1[j], b = r2[j];
        #pragma unroll
        for (int o = 8; o > 0; o >>= 1){
            a += __shfl_xor_sync(0x0000ffffu, a, o);
            b += __shfl_xor_sync(0x0000ffffu, b, o);
        }
        if (j == 0){ r1[0] = a; r2[0] = b; }
    }
    __syncthreads();
    float mu  = r1[0] * (1.0f/DM);
    float var = r2[0] * (1.0f/DM) - mu*mu;
    float v = (s - mu) * rsqrtf(var + 1e-5f) * lng[j] + lnb[j];
    if (c == 0){
        float scv = 0.9f - 0.3f*(float)sid[0];
        g_dA[n*DM + j] = v * scv;
    } else if (c == 1) g_dB[n*DM + j] = v;
    else               g_dC[n*DM + j] = v;
}

// ---------------- residual + rmsnorm (bf16 out for gemm) ----------------
__global__ void k_res(const float* __restrict__ x, const float* __restrict__ hinit,
                      const float* __restrict__ rmsw, float* __restrict__ resid){
    __shared__ float red[16];
    int m = blockIdx.x, j = threadIdx.x;     // 8192 x 512
    int n = m >> 9, t = m & 511;
    float v = x[(size_t)m*DM + j] + g_dB[n*DM + j];
    if (t == 0) v += hinit[n*DM + j];
    resid[(size_t)m*DM + j] = v;
    float s2 = v*v;
    #pragma unroll
    for (int o = 16; o > 0; o >>= 1) s2 += __shfl_xor_sync(0xffffffffu, s2, o);
    int wid = j >> 5, ln = j & 31;
    if (ln == 0) red[wid] = s2;
    __syncthreads();
    if (j < 16){
        float a = red[j];
        #pragma unroll
        for (int o = 8; o > 0; o >>= 1) a += __shfl_xor_sync(0x0000ffffu, a, o);
        if (j == 0) red[0] = a;
    }
    __syncthreads();
    float rs = rsqrtf(red[0]*(1.0f/DM) + 1e-5f);
    g_hnb[(size_t)m*DM + j] = __float2bfloat16(v * rs * rmsw[j]);
}

// ---------------- bf16 tensor-core GEMM: C[M,N] = A[M,K] * B[N,K]^T ----------------
// 8 warps. EPI: 0 plain fp32; 1 softplus(C+bias[col]); 2 fp32 + bf16 copy of col<32;
// 4 final-fusion epilogue (out/hfin).
template<int BM,int BN,int BK,int WGM,int WGN,int EPI>
__global__ void __launch_bounds__(256) gemm_bf16(
    const __nv_bfloat16* __restrict__ A, int lda,
    const __nv_bfloat16* __restrict__ B, int ldb,
    float* __restrict__ C, int ldc, int K,
    const float* __restrict__ bias,
    __nv_bfloat16* __restrict__ Cb,
    const float* __restrict__ resid, const float* __restrict__ dAp,
    const float* __restrict__ dCp, const float* __restrict__ resw,
    float* __restrict__ hfin)
{
    constexpr int PITCH = BK + 8;
    constexpr int WM = BM/WGM, WN = BN/WGN;
    constexpr int MF = WM/16, NF = WN/8;
    __shared__ __align__(16) __nv_bfloat16 sA[2][BM*PITCH];
    __shared__ __align__(16) __nv_bfloat16 sB[2][BN*PITCH];
    int tid = threadIdx.x;
    int lane = tid & 31, wid = tid >> 5;
    int wm = wid % WGM, wn = wid / WGM;
    int bm0 = blockIdx.y*BM, bn0 = blockIdx.x*BN;

    float acc[MF][NF][4];
    #pragma unroll
    for (int i = 0; i < MF; i++)
        #pragma unroll
        for (int j = 0; j < NF; j++)
            #pragma unroll
            for (int r = 0; r < 4; r++) acc[i][j][r] = 0.f;

    auto load_tile = [&](int st, int k0){
        constexpr int CA = BM*BK/8;
        #pragma unroll
        for (int c = tid; c < CA; c += 256){
            int r = c/(BK/8), c8 = c%(BK/8);
            const void* src = &A[(size_t)(bm0+r)*lda + k0 + c8*8];
            unsigned dst = (unsigned)__cvta_generic_to_shared(&sA[st][r*PITCH + c8*8]);
            asm volatile("cp.async.cg.shared.global [%0], [%1], 16;" :: "r"(dst), "l"(src));
        }
        constexpr int CB = BN*BK/8;
        #pragma unroll
        for (int c = tid; c < CB; c += 256){
            int r = c/(BK/8), c8 = c%(BK/8);
            const void* src = &B[(size_t)(bn0+r)*ldb + k0 + c8*8];
            unsigned dst = (unsigned)__cvta_generic_to_shared(&sB[st][r*PITCH + c8*8]);
            asm volatile("cp.async.cg.shared.global [%0], [%1], 16;" :: "r"(dst), "l"(src));
        }
    };

    const int KT = K / BK;
    load_tile(0, 0);
    asm volatile("cp.async.commit_group;");
    for (int kt = 0; kt < KT; kt++){
        if (kt + 1 < KT) load_tile((kt+1)&1, (kt+1)*BK);
        asm volatile("cp.async.commit_group;");
        asm volatile("cp.async.wait_group 1;");
        __syncthreads();
        int st = kt & 1;
        #pragma unroll
        for (int kc = 0; kc < BK; kc += 16){
            unsigned af[MF][4], bf[NF][2];
            #pragma unroll
            for (int mf = 0; mf < MF; mf++){
                unsigned addr = (unsigned)__cvta_generic_to_shared(
                    &sA[st][(wm*WM + mf*16 + (lane&15))*PITCH + kc + (lane>>4)*8]);
                asm volatile("ldmatrix.sync.aligned.m8n8.x4.shared.b16 {%0,%1,%2,%3}, [%4];"
                    : "=r"(af[mf][0]),"=r"(af[mf][1]),"=r"(af[mf][2]),"=r"(af[mf][3])
                    : "r"(addr));
            }
            #pragma unroll
            for (int nf = 0; nf < NF; nf++){
                unsigned addr = (unsigned)__cvta_generic_to_shared(
                    &sB[st][(wn*WN + nf*8 + (lane&7))*PITCH + kc + ((lane>>3)&1)*8]);
                asm volatile("ldmatrix.sync.aligned.m8n8.x2.shared.b16 {%0,%1}, [%2];"
                    : "=r"(bf[nf][0]),"=r"(bf[nf][1]) : "r"(addr));
            }
            #pragma unroll
            for (int mf = 0; mf < MF; mf++)
                #pragma unroll
                for (int nf = 0; nf < NF; nf++)
                    mma_bf16(acc[mf][nf], af[mf], bf[nf]);
        }
        __syncthreads();
    }

    float rw = 0.f;
    if (EPI == 4) rw = resw[0];
    #pragma unroll
    for (int mf = 0; mf < MF; mf++){
        int row0 = bm0 + wm*WM + mf*16 + (lane >> 2);
        #pragma unroll
        for (int nf = 0; nf < NF; nf++){
            int col = bn0 + wn*WN + nf*8 + (lane & 3)*2;
            float v[4] = {acc[mf][nf][0], acc[mf][nf][1], acc[mf][nf][2], acc[mf][nf][3]};
            if (EPI == 1){
                float bA = bias[col], bB = bias[col+1];
                v[0] = softplusf(v[0]+bA); v[1] = softplusf(v[1]+bB);
                v[2] = softplusf(v[2]+bA); v[3] = softplusf(v[3]+bB);
            }
            if (EPI == 4){
                #pragma unroll
                for (int h = 0; h < 2; h++){
                    int row = row0 + h*8;
                    int n = row >> 9, t = row & 511;
                    float a0 = 1.0f + 0.1f*dAp[n*DM + col];
                    float a1 = 1.0f + 0.1f*dAp[n*DM + col+1];
                    float c0 = 0.1f*dCp[n*DM + col];
                    float c1 = 0.1f*dCp[n*DM + col+1];
                    float r0 = rw*resid[(size_t)row*DM + col];
                    float r1 = rw*resid[(size_t)row*DM + col+1];
                    v[2*h]   = v[2*h]*a0 + c0 + r0;
                    v[2*h+1] = v[2*h+1]*a1 + c1 + r1;
                    if (t == LL-1){
                        hfin[n*DM + col]   = v[2*h];
                        hfin[n*DM + col+1] = v[2*h+1];
                    }
                }
            }
            *(float2*)&C[(size_t)row0*ldc + col]     = make_float2(v[0], v[1]);
            *(float2*)&C[(size_t)(row0+8)*ldc + col] = make_float2(v[2], v[3]);
            if (EPI == 2 && col < 32){
                Cb[row0*DTR + col]       = __float2bfloat16(v[0]);
                Cb[row0*DTR + col+1]     = __float2bfloat16(v[1]);
                Cb[(row0+8)*DTR + col]   = __float2bfloat16(v[2]);
                Cb[(row0+8)*DTR + col+1] = __float2bfloat16(v[3]);
            }
        }
    }
}

// ---------------- depthwise causal conv + silu, 8 outputs/thread ----------------
template<int REV>
__global__ void k_conv(const float* __restrict__ cw, const float* __restrict__ cb){
    int blk = blockIdx.x;                   // (NB*64, 4) x 256
    int n = blk >> 6, tt = (blk & 63)*8;
    int d = blockIdx.y*256 + threadIdx.x;
    const float* w = cw + d*4;
    float w0 = w[0], w1 = w[1], w2 = w[2], w3 = w[3];
    float bias = cb[d];
    float xv[11];
    #pragma unroll
    for (int j = 0; j < 11; j++){
        int tau = tt - 3 + j;
        if (tau >= 0){
            int src = REV ? (LL-1-tau) : tau;
            xv[j] = g_xz[(size_t)(n*LL + src)*(2*DI) + d];
        } else xv[j] = 0.f;
    }
    #pragma unroll
    for (int i = 0; i < 8; i++){
        float s = bias + w0*xv[i] + w1*xv[i+1] + w2*xv[i+2] + w3*xv[i+3];
        float sv = siluf(s);
        size_t m = (size_t)(n*LL + tt + i);
        g_xc[m*DI + d]  = sv;
        g_xcb[m*DI + d] = __float2bfloat16(sv);
    }
}

// ---------------- selective scan, 8-deep register prefetch ----------------
template<int ADDFLIP>
__global__ void k_scan(const float* __restrict__ Alog, const float* __restrict__ Dp,
                       float* __restrict__ y){
    int n  = blockIdx.y;
    int ch = blockIdx.x*64 + (threadIdx.x >> 2);  // (16,16) x 256
    int s0 = (threadIdx.x & 3) * 4;
    float A2[4];
    #pragma unroll
    for (int i = 0; i < 4; i++)
        A2[i] = -__expf(Alog[ch*DS + s0 + i]) * 1.44269504088896f;
    float Dv = Dp[ch];
    float h0=0.f,h1=0.f,h2=0.f,h3=0.f;
    size_t base = (size_t)n*LL;

    float pu[8], pd[8]; float4 pB[8], pC[8];
    #pragma unroll
    for (int i = 0; i < 8; i++){
        size_t r = base + i;
        pu[i] = g_xc[r*DI + ch];
        pd[i] = g_dt[r*DI + ch];
        pB[i] = *(const float4*)&g_dbl[r*64 + DTR + s0];
        pC[i] = *(const float4*)&g_dbl[r*64 + DTR + DS + s0];
    }

    for (int t0 = 0; t0 < LL; t0 += 8){
        #pragma unroll
        for (int i = 0; i < 8; i++){
            int t = t0 + i;
            float u = pu[i], dv = pd[i];
            float4 Bv = pB[i], Cv = pC[i];
            int tn = t + 8;
            if (tn < LL){
                size_t r = base + tn;
                pu[i] = g_xc[r*DI + ch];
                pd[i] = g_dt[r*DI + ch];
                pB[i] = *(const float4*)&g_dbl[r*64 + DTR + s0];
                pC[i] = *(const float4*)&g_dbl[r*64 + DTR + DS + s0];
            }
            float du = dv*u;
            h0 = exp2f(dv*A2[0])*h0 + du*Bv.x;
            h1 = exp2f(dv*A2[1])*h1 + du*Bv.y;
            h2 = exp2f(dv*A2[2])*h2 + du*Bv.z;
            h3 = exp2f(dv*A2[3])*h3 + du*Bv.w;
            float acc = h0*Cv.x + h1*Cv.y + h2*Cv.z + h3*Cv.w;
            acc += __shfl_xor_sync(0xffffffffu, acc, 1);
            acc += __shfl_xor_sync(0xffffffffu, acc, 2);
            if ((threadIdx.x & 3) == 0){
                int tout = ADDFLIP ? (LL-1-t) : t;
                float val = acc + u*Dv;
                float* py = &y[(base + tout)*DI + ch];
                if (ADDFLIP) *py += val; else *py = val;
            }
        }
    }
}

// ---------------- ys = (y_f + y_b) * silu(z) -> bf16 ----------------
__global__ void k_ymul(){
    size_t m = blockIdx.x; int d = threadIdx.x;   // 8192 x 1024
    float z = g_xz[m*(2*DI) + DI + d];
    g_xcb[m*DI + d] = __float2bfloat16(g_y[m*DI + d] * siluf(z));
}

// ---------------- launch ----------------
extern "C" void kernel_launch(void* const* d_in, const int* in_sizes, int n_in,
                              void* d_out, int out_size)
{
    const float* x      = (const float*)d_in[0];
    const int*   sid    = (const int*)  d_in[1];
    const float* h_init = (const float*)d_in[2];
    const float* W_gf   = (const float*)d_in[3];
    const float* b_gf   = (const float*)d_in[4];
    const float* emb    = (const float*)d_in[5];
    const float* W1     = (const float*)d_in[6];
    const float* b1     = (const float*)d_in[7];
    const float* W2     = (const float*)d_in[8];
    const float* b2     = (const float*)d_in[9];
    const float* W3     = (const float*)d_in[10];
    const float* b3     = (const float*)d_in[11];
    const float* ln_g   = (const float*)d_in[12];
    const float* ln_b   = (const float*)d_in[13];
    const float* rms_w  = (const float*)d_in[14];
    const float* W_in   = (const float*)d_in[15];
    const float* W_out  = (const float*)d_in[16];
    const float* res_w  = (const float*)d_in[17];
    const float* convw_f= (const float*)d_in[18];
    const float* convb_f= (const float*)d_in[19];
    const float* xproj_f= (const float*)d_in[20];
    const float* dtw_f  = (const float*)d_in[21];
    const float* dtb_f  = (const float*)d_in[22];
    const float* Alog_f = (const float*)d_in[23];
    const float* D_f    = (const float*)d_in[24];
    const float* convw_b= (const float*)d_in[25];
    const float* convb_b= (const float*)d_in[26];
    const float* xproj_b= (const float*)d_in[27];
    const float* dtw_b  = (const float*)d_in[28];
    const float* dtb_b  = (const float*)d_in[29];
    const float* Alog_b = (const float*)d_in[30];
    const float* D_b    = (const float*)d_in[31];

    float* out   = (float*)d_out;
    float* resid = out + (size_t)ROWS*DM;
    float* hfin  = out + 2*(size_t)ROWS*DM;

    float *p_xz, *p_xc, *p_dbl, *p_dt, *p_y, *p_dA, *p_dC;
    __nv_bfloat16 *p_hnb, *p_xcb, *p_dblb, *p_wb;
    cudaGetSymbolAddress((void**)&p_xz,  g_xz);
    cudaGetSymbolAddress((void**)&p_xc,  g_xc);
    cudaGetSymbolAddress((void**)&p_dbl, g_dbl);
    cudaGetSymbolAddress((void**)&p_dt,  g_dt);
    cudaGetSymbolAddress((void**)&p_y,   g_y);
    cudaGetSymbolAddress((void**)&p_dA,  g_dA);
    cudaGetSymbolAddress((void**)&p_dC,  g_dC);
    cudaGetSymbolAddress((void**)&p_hnb, g_hnb);
    cudaGetSymbolAddress((void**)&p_xcb, g_xcb);
    cudaGetSymbolAddress((void**)&p_dblb,g_dblb);
    cudaGetSymbolAddress((void**)&p_wb,  g_wb);

    // weight conversions (bf16)
    k_cvt<<<4096, 256>>>(W_in,    p_wb + OFF_WIN,  2*DI*DM);
    k_cvt<<<2048, 256>>>(W_out,   p_wb + OFF_WOUT, DM*DI);
    k_cvt<<<256,  256>>>(xproj_f, p_wb + OFF_XPF,  64*DI);
    k_cvt<<<256,  256>>>(xproj_b, p_wb + OFF_XPB,  64*DI);
    k_cvt<<<128,  256>>>(dtw_f,   p_wb + OFF_DTWF, DI*DTR);
    k_cvt<<<128,  256>>>(dtw_b,   p_wb + OFF_DTWB, DI*DTR);

    // conditioning path
    k_meanp<<<dim3(NB,8), DM>>>(x);
    k_gf<<<dim3(NB,16), 256>>>(W_gf, b_gf);
    k_h1<<<dim3(NB,64), 256>>>(W1, b1, emb, sid);
    k_h2<<<dim3(NB,64), 256>>>(W2, b2);
    k_offmm<<<dim3(NB,192), 256>>>(W3, b3);
    k_offln<<<dim3(NB,3), DM>>>(ln_g, ln_b, sid);

    // residual + rmsnorm (bf16 out)
    k_res<<<ROWS, DM>>>(x, h_init, rms_w, resid);

    // xz = hn @ W_in.T  (8192 x 2048, K=512)
    gemm_bf16<128,128,32,2,4,0><<<dim3(16, 64), 256>>>(
        p_hnb, DM, p_wb + OFF_WIN, DM, p_xz, 2*DI, DM,
        nullptr, nullptr, nullptr, nullptr, nullptr, nullptr, nullptr);

    // forward direction
    k_conv<0><<<dim3(NB*64,4), 256>>>(convw_f, convb_f);
    gemm_bf16<64,64,32,2,4,2><<<dim3(1, 128), 256>>>(
        p_xcb, DI, p_wb + OFF_XPF, DI, p_dbl, 64, DI,
        nullptr, p_dblb, nullptr, nullptr, nullptr, nullptr, nullptr);
    gemm_bf16<128,128,32,2,4,1><<<dim3(8, 64), 256>>>(
        p_dblb, DTR, p_wb + OFF_DTWF, DTR, p_dt, DI, DTR,
        dtb_f, nullptr, nullptr, nullptr, nullptr, nullptr, nullptr);
    k_scan<0><<<dim3(16, NB), 256>>>(Alog_f, D_f, p_y);

    // backward direction
    k_conv<1><<<dim3(NB*64,4), 256>>>(convw_b, convb_b);
    gemm_bf16<64,64,32,2,4,2><<<dim3(1, 128), 256>>>(
        p_xcb, DI, p_wb + OFF_XPB, DI, p_dbl, 64, DI,
        nullptr, p_dblb, nullptr, nullptr, nullptr, nullptr, nullptr);
    gemm_bf16<128,128,32,2,4,1><<<dim3(8, 64), 256>>>(
        p_dblb, DTR, p_wb + OFF_DTWB, DTR, p_dt, DI, DTR,
        dtb_b, nullptr, nullptr, nullptr, nullptr, nullptr, nullptr);
    k_scan<1><<<dim3(16, NB), 256>>>(Alog_b, D_b, p_y);

    // gating -> bf16, then W_out gemm with fused final epilogue
    k_ymul<<<ROWS, DI>>>();
    gemm_bf16<128,128,32,2,4,4><<<dim3(4, 64), 256>>>(
        p_xcb, DI, p_wb + OFF_WOUT, DI, out, DM, DI,
        nullptr, nullptr, resid, p_dA, p_dC, res_w, hfin);
}